// round 15
// baseline (speedup 1.0000x reference)
#include <cuda_runtime.h>
#include <cuda_bf16.h>
#include <cuda_fp16.h>
#include <math.h>
#include <stdint.h>

#define B_   2
#define S_   2048
#define DM_  2048
#define H_   16
#define DH_  128
#define BSM  (B_ * S_)   // 4096 rows

// ---------------------------------------------------------------------------
// Scratch (static device globals — no allocation allowed)
// ---------------------------------------------------------------------------
__device__ float g_q [(size_t)BSM * DM_];
__device__ float g_k [(size_t)BSM * DM_];
__device__ __nv_bfloat16 g_xh[(size_t)BSM * DM_];
__device__ __nv_bfloat16 g_xl[(size_t)BSM * DM_];
__device__ __half        g_xf[(size_t)BSM * DM_];
__device__ __nv_bfloat16 g_qh[(size_t)BSM * DM_];
__device__ __nv_bfloat16 g_ql[(size_t)BSM * DM_];
__device__ __nv_bfloat16 g_kh[(size_t)BSM * DM_];
__device__ __nv_bfloat16 g_kl[(size_t)BSM * DM_];
__device__ __half        g_vtf[(size_t)BSM * DM_];
__device__ __nv_bfloat16 g_oh[(size_t)BSM * DM_];
__device__ __nv_bfloat16 g_ol[(size_t)BSM * DM_];
__device__ __half        g_wqf[(size_t)DM_ * DM_];
__device__ __half        g_wkf[(size_t)DM_ * DM_];
__device__ __nv_bfloat16 g_wvh[(size_t)DM_ * DM_];
__device__ __nv_bfloat16 g_wvl[(size_t)DM_ * DM_];
__device__ __nv_bfloat16 g_woh[(size_t)DM_ * DM_];
__device__ __nv_bfloat16 g_wol[(size_t)DM_ * DM_];

// ---------------------------------------------------------------------------
// Helpers
// ---------------------------------------------------------------------------
__device__ __forceinline__ void mma_bf16(float* c, const uint32_t* a, const uint32_t* b) {
    asm volatile(
        "mma.sync.aligned.m16n8k16.row.col.f32.bf16.bf16.f32 "
        "{%0,%1,%2,%3}, {%4,%5,%6,%7}, {%8,%9}, {%0,%1,%2,%3};"
        : "+f"(c[0]), "+f"(c[1]), "+f"(c[2]), "+f"(c[3])
        : "r"(a[0]), "r"(a[1]), "r"(a[2]), "r"(a[3]), "r"(b[0]), "r"(b[1]));
}
__device__ __forceinline__ void mma_f16(float* c, const uint32_t* a, const uint32_t* b) {
    asm volatile(
        "mma.sync.aligned.m16n8k16.row.col.f32.f16.f16.f32 "
        "{%0,%1,%2,%3}, {%4,%5,%6,%7}, {%8,%9}, {%0,%1,%2,%3};"
        : "+f"(c[0]), "+f"(c[1]), "+f"(c[2]), "+f"(c[3])
        : "r"(a[0]), "r"(a[1]), "r"(a[2]), "r"(a[3]), "r"(b[0]), "r"(b[1]));
}

__device__ __forceinline__ void ldsm4(uint32_t& r0, uint32_t& r1, uint32_t& r2,
                                      uint32_t& r3, uint32_t saddr) {
    asm volatile("ldmatrix.sync.aligned.m8n8.x4.shared.b16 {%0,%1,%2,%3}, [%4];"
                 : "=r"(r0), "=r"(r1), "=r"(r2), "=r"(r3) : "r"(saddr));
}

__device__ __forceinline__ uint32_t smem_u32(const void* p) {
    return (uint32_t)__cvta_generic_to_shared(p);
}

__device__ __forceinline__ void cp16(void* smem_dst, const void* gmem_src) {
    uint32_t sa = (uint32_t)__cvta_generic_to_shared(smem_dst);
    asm volatile("cp.async.cg.shared.global [%0], [%1], 16;" :: "r"(sa), "l"(gmem_src));
}
__device__ __forceinline__ void cp_commit() { asm volatile("cp.async.commit_group;"); }
__device__ __forceinline__ void cp_wait1() { asm volatile("cp.async.wait_group 1;"); }
__device__ __forceinline__ void cp_wait0() { asm volatile("cp.async.wait_group 0;"); }

__device__ __forceinline__ void bfsplit1(float x, __nv_bfloat16& h, __nv_bfloat16& l) {
    h = __float2bfloat16_rn(x);
    l = __float2bfloat16_rn(x - __bfloat162float(h));
}
__device__ __forceinline__ uint32_t packbf(__nv_bfloat16 e, __nv_bfloat16 o) {
    uint32_t lo = __bfloat16_as_ushort(e), hi = __bfloat16_as_ushort(o);
    return lo | (hi << 16);
}
__device__ __forceinline__ void packsplit2(float a, float b, uint32_t& wh, uint32_t& wl) {
    __nv_bfloat16 ha, la, hb, lb;
    bfsplit1(a, ha, la); bfsplit1(b, hb, lb);
    wh = packbf(ha, hb); wl = packbf(la, lb);
}
__device__ __forceinline__ uint32_t packh(__half a, __half b) {
    return (uint32_t)__half_as_ushort(a) | ((uint32_t)__half_as_ushort(b) << 16);
}
__device__ __forceinline__ void hpacksplit2(float a, float b, uint32_t& wh, uint32_t& wl) {
    __half ha = __float2half_rn(a), hb = __float2half_rn(b);
    __half la = __float2half_rn(a - __half2float(ha));
    __half lb = __float2half_rn(b - __half2float(hb));
    wh = packh(ha, hb); wl = packh(la, lb);
}

// ---------------------------------------------------------------------------
// Fused pre-pass (single launch)
// ---------------------------------------------------------------------------
#define XN4_ (BSM * DM_ / 4)
#define WN4_ (DM_ * DM_ / 4)

__global__ __launch_bounds__(256)
void prepass_all(
    const float4* __restrict__ x,  uint2* __restrict__ xh, uint2* __restrict__ xl,
    uint2* __restrict__ xf,
    const float4* __restrict__ wq, uint2* __restrict__ wqf,
    const float4* __restrict__ wk, uint2* __restrict__ wkf,
    const float4* __restrict__ wv, uint2* __restrict__ wvh, uint2* __restrict__ wvl,
    const float4* __restrict__ wo, uint2* __restrict__ woh, uint2* __restrict__ wol) {
    int i = blockIdx.x * blockDim.x + threadIdx.x;
    if (i < XN4_) {
        float4 v = x[i];
        __nv_bfloat16 h0, l0, h1, l1, h2, l2, h3, l3;
        bfsplit1(v.x, h0, l0); bfsplit1(v.y, h1, l1);
        bfsplit1(v.z, h2, l2); bfsplit1(v.w, h3, l3);
        xh[i] = make_uint2(packbf(h0, h1), packbf(h2, h3));
        xl[i] = make_uint2(packbf(l0, l1), packbf(l2, l3));
        xf[i] = make_uint2(packh(__float2half_rn(v.x), __float2half_rn(v.y)),
                           packh(__float2half_rn(v.z), __float2half_rn(v.w)));
        return;
    }
    int t = i - XN4_;
    int r = t >> 20;
    int j = t & (WN4_ - 1);
    if (r < 2) {
        float4 v = (r == 0 ? wq : wk)[j];
        uint2* dst = (r == 0 ? wqf : wkf);
        dst[j] = make_uint2(packh(__float2half_rn(v.x), __float2half_rn(v.y)),
                            packh(__float2half_rn(v.z), __float2half_rn(v.w)));
    } else {
        float4 v = (r == 2 ? wv : wo)[j];
        uint2* hi = (r == 2 ? wvh : woh);
        uint2* lo = (r == 2 ? wvl : wol);
        __nv_bfloat16 h0, l0, h1, l1, h2, l2, h3, l3;
        bfsplit1(v.x, h0, l0); bfsplit1(v.y, h1, l1);
        bfsplit1(v.z, h2, l2); bfsplit1(v.w, h3, l3);
        hi[j] = make_uint2(packbf(h0, h1), packbf(h2, h3));
        lo[j] = make_uint2(packbf(l0, l1), packbf(l2, l3));
    }
}

// ---------------------------------------------------------------------------
// fp16 SINGLE-PASS GEMM (wq/wk): 128x128x32, 256 thr, 2 CTAs/SM,
// 3-stage cp.async pipeline, ONE sync per ktile, issue-before-compute.
// ---------------------------------------------------------------------------
#define TWB 2560
#define STG1W (2 * TWB)
#define GEMM1_SMEM (3 * STG1W * 4)

__global__ __launch_bounds__(256, 2)
void gemm_f16s(const __half* __restrict__ A, const __half* __restrict__ Bw,
               float* __restrict__ C) {
    extern __shared__ uint32_t smw[];
    const uint32_t smem_b = smem_u32(smw);

    const int tid  = threadIdx.x;
    const int lane = tid & 31;
    const int w    = tid >> 5;
    const int wm   = w & 3;
    const int wn   = w >> 2;
    const int g    = lane >> 2;
    const int tg   = lane & 3;
    const int rb   = wm * 32;
    const int cb   = wn * 64;
    const int K    = DM_;

    const __half* gA = A  + (size_t)blockIdx.y * 128 * K;
    const __half* gB = Bw + (size_t)blockIdx.x * 128 * K;

    const uint32_t a_off = (uint32_t)((rb + (lane & 15)) * 20 + (lane >> 4) * 4) * 4;
    const uint32_t b_off = (uint32_t)((cb + (lane & 7) + ((lane >> 4) & 1) * 8) * 20
                                      + ((lane >> 3) & 1) * 4) * 4;

    auto issue = [&](int stage, int k0) {
        uint32_t* base = smw + stage * STG1W;
#pragma unroll
        for (int p = 0; p < 2; p++) {
            int s   = p * 256 + tid;
            int row = s >> 2;
            int kq  = s & 3;
            int d   = row * 20 + kq * 4;
            size_t srcoff = (size_t)row * K + k0 + kq * 8;
            cp16(base + d,       gA + srcoff);
            cp16(base + TWB + d, gB + srcoff);
        }
        cp_commit();
    };

    float acc[2][8][4];
#pragma unroll
    for (int mt = 0; mt < 2; mt++)
#pragma unroll
        for (int nt = 0; nt < 8; nt++)
#pragma unroll
            for (int i = 0; i < 4; i++) acc[mt][nt][i] = 0.f;

    issue(0, 0);
    issue(1, 32);

    const int KT = K / 32;
    int stg = 0;
    for (int kt = 0; kt < KT; kt++) {
        if (kt == KT - 1) cp_wait0(); else cp_wait1();
        __syncthreads();
        if (kt + 2 < KT) issue((stg + 2) % 3, (kt + 2) * 32);

        const uint32_t tb = smem_b + stg * (STG1W * 4);
#pragma unroll
        for (int kc = 0; kc < 2; kc++) {
            const uint32_t kbb = kc * 32;
            uint32_t ah[2][4];
#pragma unroll
            for (int mt = 0; mt < 2; mt++)
                ldsm4(ah[mt][0], ah[mt][1], ah[mt][2], ah[mt][3],
                      tb + a_off + mt * (16 * 80) + kbb);
#pragma unroll
            for (int p = 0; p < 4; p++) {
                uint32_t bh[2][2];
                ldsm4(bh[0][0], bh[0][1], bh[1][0], bh[1][1],
                      tb + TWB * 4 + b_off + p * (16 * 80) + kbb);
#pragma unroll
                for (int q = 0; q < 2; q++)
#pragma unroll
                    for (int mt = 0; mt < 2; mt++)
                        mma_f16(acc[mt][2 * p + q], ah[mt], bh[q]);
            }
        }
        stg = (stg + 1) % 3;
    }

#pragma unroll
    for (int mt = 0; mt < 2; mt++)
#pragma unroll
        for (int nt = 0; nt < 8; nt++) {
            int row = blockIdx.y * 128 + rb + mt * 16 + g;
            int col = blockIdx.x * 128 + cb + nt * 8 + tg * 2;
            *(float2*)(C + (size_t)row * DM_ + col) =
                make_float2(acc[mt][nt][0], acc[mt][nt][1]);
            *(float2*)(C + (size_t)(row + 8) * DM_ + col) =
                make_float2(acc[mt][nt][2], acc[mt][nt][3]);
        }
}

// ---------------------------------------------------------------------------
// bf16x3 GEMM (wv, wo): 128Mx256N, 512 threads, 3-stage, 1 sync/ktile.
// Pass-major mma ordering within each p-group (acc reuse distance 4).
// OUT=0: fp32 C. OUT=1: V path — fp16 single transposed per-head store.
// ---------------------------------------------------------------------------
#define AT_W 2560
#define BT_W 5120
#define STG3W (2 * AT_W + 2 * BT_W)
#define GEMM_SMEM (3 * STG3W * 4)

template<int OUT>
__global__ __launch_bounds__(512, 1)
void gemm_bf3(const __nv_bfloat16* __restrict__ Ah, const __nv_bfloat16* __restrict__ Al,
              const __nv_bfloat16* __restrict__ Bh, const __nv_bfloat16* __restrict__ Bl,
              float* __restrict__ C, __half* __restrict__ Vf) {
    extern __shared__ uint32_t smw[];
    const uint32_t smem_b = smem_u32(smw);

    const int tid  = threadIdx.x;
    const int lane = tid & 31;
    const int w    = tid >> 5;
    const int wm   = w & 3;
    const int wn   = w >> 2;
    const int g    = lane >> 2;
    const int tg   = lane & 3;
    const int rb   = wm * 32;
    const int cb   = wn * 64;
    const int K    = DM_;

    const __nv_bfloat16* gAh = Ah + (size_t)blockIdx.y * 128 * K;
    const __nv_bfloat16* gAl = Al + (size_t)blockIdx.y * 128 * K;
    const __nv_bfloat16* gBh = Bh + (size_t)blockIdx.x * 256 * K;
    const __nv_bfloat16* gBl = Bl + (size_t)blockIdx.x * 256 * K;

    const uint32_t a_off = (uint32_t)((rb + (lane & 15)) * 20 + (lane >> 4) * 4) * 4;
    const uint32_t b_off = (uint32_t)((cb + (lane & 7) + ((lane >> 4) & 1) * 8) * 20
                                      + ((lane >> 3) & 1) * 4) * 4;

    auto issue = [&](int stage, int k0) {
        uint32_t* base = smw + stage * STG3W;
#pragma unroll
        for (int p = 0; p < 6; p++) {
            int c    = p * 512 + tid;
            int row  = c >> 2;
            int kq   = c & 3;
            const __nv_bfloat16* src;
            uint32_t* dst;
            if (row < 256) {
                int r = row & 127;
                src = (row < 128 ? gAh : gAl) + (size_t)r * K + k0 + kq * 8;
                dst = base + (row < 128 ? 0 : AT_W) + r * 20 + kq * 4;
            } else {
                int r = (row - 256) & 255;
                src = (row < 512 ? gBh : gBl) + (size_t)r * K + k0 + kq * 8;
                dst = base + 2 * AT_W + (row < 512 ? 0 : BT_W) + r * 20 + kq * 4;
            }
            cp16(dst, src);
        }
        cp_commit();
    };

    float acc[2][8][4];
#pragma unroll
    for (int mt = 0; mt < 2; mt++)
#pragma unroll
        for (int nt = 0; nt < 8; nt++)
#pragma unroll
            for (int i = 0; i < 4; i++) acc[mt][nt][i] = 0.f;

    issue(0, 0);
    issue(1, 32);

    const int KT = K / 32;
    int stg = 0;
    for (int kt = 0; kt < KT; kt++) {
        if (kt == KT - 1) cp_wait0(); else cp_wait1();
        __syncthreads();
        if (kt + 2 < KT) issue((stg + 2) % 3, (kt + 2) * 32);

        const uint32_t tb  = smem_b + stg * (STG3W * 4);
        const uint32_t tbB = tb + 2 * AT_W * 4;
#pragma unroll
        for (int kc = 0; kc < 2; kc++) {
            const uint32_t kbb = kc * 32;
            uint32_t ah[2][4], al[2][4];
#pragma unroll
            for (int mt = 0; mt < 2; mt++) {
                ldsm4(ah[mt][0], ah[mt][1], ah[mt][2], ah[mt][3],
                      tb + a_off + mt * (16 * 80) + kbb);
                ldsm4(al[mt][0], al[mt][1], al[mt][2], al[mt][3],
                      tb + AT_W * 4 + a_off + mt * (16 * 80) + kbb);
            }
#pragma unroll
            for (int p = 0; p < 4; p++) {
                uint32_t bh[2][2], bl[2][2];
                ldsm4(bh[0][0], bh[0][1], bh[1][0], bh[1][1],
                      tbB + b_off + p * (16 * 80) + kbb);
                ldsm4(bl[0][0], bl[0][1], bl[1][0], bl[1][1],
                      tbB + BT_W * 4 + b_off + p * (16 * 80) + kbb);
                // pass-major: all hh, then all hl, then all lh (acc distance 4)
#pragma unroll
                for (int q = 0; q < 2; q++)
#pragma unroll
                    for (int mt = 0; mt < 2; mt++)
                        mma_bf16(acc[mt][2 * p + q], ah[mt], bh[q]);
#pragma unroll
                for (int q = 0; q < 2; q++)
#pragma unroll
                    for (int mt = 0; mt < 2; mt++)
                        mma_bf16(acc[mt][2 * p + q], ah[mt], bl[q]);
#pragma unroll
                for (int q = 0; q < 2; q++)
#pragma unroll
                    for (int mt = 0; mt < 2; mt++)
                        mma_bf16(acc[mt][2 * p + q], al[mt], bh[q]);
            }
        }
        stg = (stg + 1) % 3;
    }

#pragma unroll
    for (int mt = 0; mt < 2; mt++)
#pragma unroll
        for (int nt = 0; nt < 8; nt++) {
            int row = blockIdx.y * 128 + rb + mt * 16 + g;
            int col = blockIdx.x * 256 + cb + nt * 8 + tg * 2;
            if (OUT == 0) {
                *(float2*)(C + (size_t)row * DM_ + col) =
                    make_float2(acc[mt][nt][0], acc[mt][nt][1]);
                *(float2*)(C + (size_t)(row + 8) * DM_ + col) =
                    make_float2(acc[mt][nt][2], acc[mt][nt][3]);
            } else {
                int hh = col >> 7, d = col & 127;
#pragma unroll
                for (int rr = 0; rr < 2; rr++) {
                    int r = row + rr * 8;
                    int bb = r >> 11, s = r & 2047;
                    size_t base = ((size_t)(bb * 16 + hh) * 128 + d) * 2048 + s;
                    Vf[base]        = __float2half_rn(acc[mt][nt][rr * 2]);
                    Vf[base + 2048] = __float2half_rn(acc[mt][nt][rr * 2 + 1]);
                }
            }
        }
}

// ---------------------------------------------------------------------------
// Fused RMSNorm + RoPE + bf16 split for BOTH q and k in one launch.
// ---------------------------------------------------------------------------
__global__ __launch_bounds__(256)
void norm_rope_split2(const float* __restrict__ qin, const float* __restrict__ kin,
                      const float* __restrict__ rope,
                      const float* __restrict__ qw, const float* __restrict__ kw,
                      __nv_bfloat16* __restrict__ qoh, __nv_bfloat16* __restrict__ qol,
                      __nv_bfloat16* __restrict__ koh, __nv_bfloat16* __restrict__ kol) {
    int warp = (blockIdx.x * blockDim.x + threadIdx.x) >> 5;
    int lane = threadIdx.x & 31;
    const int half = BSM * H_;
    if (warp >= 2 * half) return;
    bool isk = warp >= half;
    if (isk) warp -= half;
    const float* t = isk ? kin : qin;
    const float* w = isk ? kw : qw;
    __nv_bfloat16* outh = isk ? koh : qoh;
    __nv_bfloat16* outl = isk ? kol : qol;
    float scale = isk ? 1.0f : 0.08838834764831845f;

    int h  = warp % H_;
    int bs = warp / H_;
    int s  = bs % S_;
    int b  = bs / S_;

    const float* row = t + (size_t)bs * DM_ + h * DH_;
    float4 v4 = *(const float4*)(row + 4 * lane);
    float v[4] = { v4.x, v4.y, v4.z, v4.w };

    float ss = v[0] * v[0] + v[1] * v[1] + v[2] * v[2] + v[3] * v[3];
#pragma unroll
    for (int o = 16; o; o >>= 1) ss += __shfl_xor_sync(0xFFFFFFFFu, ss, o);
    float inv = rsqrtf(ss * (1.0f / 128.0f) + 1e-6f);
    const float4 w4 = *(const float4*)(w + 4 * lane);
    v[0] *= inv * w4.x; v[1] *= inv * w4.y; v[2] *= inv * w4.z; v[3] *= inv * w4.w;

    float pv[4];
#pragma unroll
    for (int j = 0; j < 4; j++) pv[j] = __shfl_xor_sync(0xFFFFFFFFu, v[j], 16);

    const float* f = rope + (size_t)s * 256;
    float y[4];
#pragma unroll
    for (int j = 0; j < 4; j++) {
        int d = 4 * lane + j;
        int i = d & 63;
        float a, bb;
        if (lane < 16) { a = f[i * 4 + 0]; bb = f[i * 4 + 1]; y[j] = a * v[j] + bb * pv[j]; }
        else           { a = f[i * 4 + 2]; bb = f[i * 4 + 3]; y[j] = a * pv[j] + bb * v[j]; }
        y[j] *= scale;
    }

    __nv_bfloat16 hh[4], ll[4];
#pragma unroll
    for (int j = 0; j < 4; j++) bfsplit1(y[j], hh[j], ll[j]);

    size_t base = ((size_t)(b * H_ + h) * S_ + s) * DH_ + 4 * lane;
    *(uint2*)(outh + base) = make_uint2(packbf(hh[0], hh[1]), packbf(hh[2], hh[3]));
    *(uint2*)(outl + base) = make_uint2(packbf(ll[0], ll[1]), packbf(ll[2], ll[3]));
}

// ---------------------------------------------------------------------------
// Register-resident flash attention.
// QK: bf16x3 pass-major. PV: fp16 x2 pass-major (distance 16).
// 3-stage KV pipeline, single sync/ktile, issue-before-compute.
// ---------------------------------------------------------------------------
#define FQW 68
#define FVW 36
#define QWORDS (128 * FQW)          // 8704 per Qh/Ql
#define KTILEW (64 * FQW)           // 4352
#define VTILEW (128 * FVW)          // 4608
#define STGW   (2 * KTILEW + VTILEW)  // 13312
#define OFF_STG (2 * QWORDS)        // 17408
#define FLASH_SMEM ((OFF_STG + 3 * STGW) * 4)   // 229376 B

__global__ __launch_bounds__(256, 1)
void flash_reg(const __nv_bfloat16* __restrict__ Qh, const __nv_bfloat16* __restrict__ Ql,
               const __nv_bfloat16* __restrict__ Kh, const __nv_bfloat16* __restrict__ Kl,
               const __half* __restrict__ Vtf,
               __nv_bfloat16* __restrict__ Oh, __nv_bfloat16* __restrict__ Ol) {
    extern __shared__ uint32_t smw[];

    const int tid  = threadIdx.x;
    const int lane = tid & 31;
    const int w    = tid >> 5;
    const int g    = lane >> 2;
    const int tg   = lane & 3;
    const int q0   = blockIdx.x * 128;
    const int h    = blockIdx.y;
    const int b    = blockIdx.z;
    const int rw   = w * 16;

    const size_t headQ = ((size_t)(b * H_ + h) * S_) * DH_;
    const __nv_bfloat16* gQh = Qh + headQ + (size_t)q0 * DH_;
    const __nv_bfloat16* gQl = Ql + headQ + (size_t)q0 * DH_;
    const __nv_bfloat16* gKh = Kh + headQ;
    const __nv_bfloat16* gKl = Kl + headQ;
    const size_t headV = ((size_t)(b * H_ + h) * DH_) * S_;
    const __half* gVtf = Vtf + headV;

    // Q load (group 1)
    {
#pragma unroll
        for (int p = 0; p < 16; p++) {
            int t   = p * 256 + tid;
            int reg = t >> 11;
            int idx = t & 2047;
            int row = idx >> 4, ch = idx & 15;
            const __nv_bfloat16* src = (reg ? gQl : gQh) + (size_t)row * DH_ + ch * 8;
            cp16(smw + reg * QWORDS + row * FQW + ch * 4, src);
        }
        cp_commit();
    }

    auto issue_kv = [&](int stage, int j0) {
        uint32_t* base = smw + OFF_STG + stage * STGW;
#pragma unroll
        for (int p = 0; p < 12; p++) {
            int t   = p * 256 + tid;
            int reg = t >> 10;
            int idx = t & 1023;
            if (reg < 2) {
                int row = idx >> 4, ch = idx & 15;
                const __nv_bfloat16* src = (reg ? gKl : gKh) + (size_t)(j0 + row) * DH_ + ch * 8;
                cp16(base + reg * KTILEW + row * FQW + ch * 4, src);
            } else {
                int d = idx >> 3, ch = idx & 7;
                const __half* src = gVtf + (size_t)d * S_ + j0 + ch * 8;
                cp16(base + 2 * KTILEW + d * FVW + ch * 4, src);
            }
        }
        cp_commit();
    };

    issue_kv(0, 0);
    issue_kv(1, 64);

    float oacc[16][4];
#pragma unroll
    for (int nt = 0; nt < 16; nt++)
#pragma unroll
        for (int i = 0; i < 4; i++) oacc[nt][i] = 0.f;
    float m0 = -1e30f, m1 = -1e30f, l0 = 0.f, l1 = 0.f;

    const int NKT = S_ / 64;
    int stg = 0;
    for (int kt = 0; kt < NKT; kt++) {
        if (kt == NKT - 1) cp_wait0(); else cp_wait1();
        __syncthreads();
        if (kt + 2 < NKT) issue_kv((stg + 2) % 3, (kt + 2) * 64);

        const uint32_t* Ksh = smw + OFF_STG + stg * STGW;
        const uint32_t* Ksl = Ksh + KTILEW;
        const uint32_t* Vsf = Ksh + 2 * KTILEW;

        // ---- scores: bf16x3, pass-major (acc reuse distance 8) ----
        float sc[8][4];
#pragma unroll
        for (int nt = 0; nt < 8; nt++)
#pragma unroll
            for (int i = 0; i < 4; i++) sc[nt][i] = 0.f;

#pragma unroll
        for (int c = 0; c < 8; c++) {
            int q0w = (rw + g) * FQW + c * 8 + tg;
            int q1w = q0w + 8 * FQW;
            uint32_t ah[4] = { smw[q0w], smw[q1w], smw[q0w + 4], smw[q1w + 4] };
            uint32_t al[4] = { smw[QWORDS + q0w], smw[QWORDS + q1w],
                               smw[QWORDS + q0w + 4], smw[QWORDS + q1w + 4] };
            uint32_t kh[8][2], kl[8][2];
#pragma unroll
            for (int nt = 0; nt < 8; nt++) {
                int n = (nt * 8 + g) * FQW + c * 8 + tg;
                kh[nt][0] = Ksh[n]; kh[nt][1] = Ksh[n + 4];
                kl[nt][0] = Ksl[n]; kl[nt][1] = Ksl[n + 4];
            }
#pragma unroll
            for (int nt = 0; nt < 8; nt++) mma_bf16(sc[nt], ah, kh[nt]);
#pragma unroll
            for (int nt = 0; nt < 8; nt++) mma_bf16(sc[nt], ah, kl[nt]);
#pragma unroll
            for (int nt = 0; nt < 8; nt++) mma_bf16(sc[nt], al, kh[nt]);
        }

        // ---- online softmax in registers ----
        {
            float mx0 = sc[0][0], mx1 = sc[0][2];
#pragma unroll
            for (int j = 0; j < 8; j++) {
                mx0 = fmaxf(mx0, fmaxf(sc[j][0], sc[j][1]));
                mx1 = fmaxf(mx1, fmaxf(sc[j][2], sc[j][3]));
            }
            mx0 = fmaxf(mx0, __shfl_xor_sync(0xFFFFFFFFu, mx0, 1));
            mx0 = fmaxf(mx0, __shfl_xor_sync(0xFFFFFFFFu, mx0, 2));
            mx1 = fmaxf(mx1, __shfl_xor_sync(0xFFFFFFFFu, mx1, 1));
            mx1 = fmaxf(mx1, __shfl_xor_sync(0xFFFFFFFFu, mx1, 2));
            float nm0 = fmaxf(m0, mx0), nm1 = fmaxf(m1, mx1);
            float a0 = __expf(m0 - nm0), a1 = __expf(m1 - nm1);
            m0 = nm0; m1 = nm1;
            float s0 = 0.f, s1 = 0.f;
#pragma unroll
            for (int j = 0; j < 8; j++) {
                sc[j][0] = __expf(sc[j][0] - m0); sc[j][1] = __expf(sc[j][1] - m0);
                sc[j][2] = __expf(sc[j][2] - m1); sc[j][3] = __expf(sc[j][3] - m1);
                s0 += sc[j][0] + sc[j][1];
                s1 += sc[j][2] + sc[j][3];
            }
            s0 += __shfl_xor_sync(0xFFFFFFFFu, s0, 1);
            s0 += __shfl_xor_sync(0xFFFFFFFFu, s0, 2);
            s1 += __shfl_xor_sync(0xFFFFFFFFu, s1, 1);
            s1 += __shfl_xor_sync(0xFFFFFFFFu, s1, 2);
            l0 = l0 * a0 + s0;
            l1 = l1 * a1 + s1;
#pragma unroll
            for (int nt = 0; nt < 16; nt++) {
                oacc[nt][0] *= a0; oacc[nt][1] *= a0;
                oacc[nt][2] *= a1; oacc[nt][3] *= a1;
            }
        }

        // ---- PV (fp16 x2), pass-major (acc reuse distance 16) ----
#pragma unroll
        for (int c = 0; c < 4; c++) {
            uint32_t ph[4], pl[4];
            hpacksplit2(sc[2 * c][0],     sc[2 * c][1],     ph[0], pl[0]);
            hpacksplit2(sc[2 * c][2],     sc[2 * c][3],     ph[1], pl[1]);
            hpacksplit2(sc[2 * c + 1][0], sc[2 * c + 1][1], ph[2], pl[2]);
            hpacksplit2(sc[2 * c + 1][2], sc[2 * c + 1][3], ph[3], pl[3]);
            uint32_t vv[16][2];
#pragma unroll
            for (int nt = 0; nt < 16; nt++) {
                int n = (nt * 8 + g) * FVW + c * 8 + tg;
                vv[nt][0] = Vsf[n]; vv[nt][1] = Vsf[n + 4];
            }
#pragma unroll
            for (int nt = 0; nt < 16; nt++) mma_f16(oacc[nt], ph, vv[nt]);
#pragma unroll
            for (int nt = 0; nt < 16; nt++) mma_f16(oacc[nt], pl, vv[nt]);
        }

        stg = (stg + 1) % 3;
    }

    {
        float li0 = 1.0f / l0, li1 = 1.0f / l1;
        size_t tok0 = (size_t)(b * S_ + q0 + rw + g) * DM_ + h * DH_;
        size_t tok1 = tok0 + 8 * DM_;
#pragma unroll
        for (int nt = 0; nt < 16; nt++) {
            int col = nt * 8 + tg * 2;
            uint32_t wh, wl;
            packsplit2(oacc[nt][0] * li0, oacc[nt][1] * li0, wh, wl);
            *(uint32_t*)(Oh + tok0 + col) = wh;
            *(uint32_t*)(Ol + tok0 + col) = wl;
            packsplit2(oacc[nt][2] * li1, oacc[nt][3] * li1, wh, wl);
            *(uint32_t*)(Oh + tok1 + col) = wh;
            *(uint32_t*)(Ol + tok1 + col) = wl;
        }
    }
}

// ---------------------------------------------------------------------------
extern "C" void kernel_launch(void* const* d_in, const int* in_sizes, int n_in,
                              void* d_out, int out_size) {
    const float* x    = (const float*)d_in[0];
    const float* rope = (const float*)d_in[1];
    const float* wq   = (const float*)d_in[2];
    const float* wk   = (const float*)d_in[3];
    const float* wv   = (const float*)d_in[4];
    const float* wo   = (const float*)d_in[5];
    const float* qnw  = (const float*)d_in[6];
    const float* knw  = (const float*)d_in[7];
    float* out = (float*)d_out;

    float *q, *k;
    __nv_bfloat16 *xh, *xl, *qh, *ql, *kh, *kl, *oh, *ol;
    __nv_bfloat16 *wvh, *wvl, *woh, *wol;
    __half *xf, *wqf, *wkf, *vtf;
    cudaGetSymbolAddress((void**)&q,   g_q);
    cudaGetSymbolAddress((void**)&k,   g_k);
    cudaGetSymbolAddress((void**)&xh,  g_xh);
    cudaGetSymbolAddress((void**)&xl,  g_xl);
    cudaGetSymbolAddress((void**)&xf,  g_xf);
    cudaGetSymbolAddress((void**)&qh,  g_qh);
    cudaGetSymbolAddress((void**)&ql,  g_ql);
    cudaGetSymbolAddress((void**)&kh,  g_kh);
    cudaGetSymbolAddress((void**)&kl,  g_kl);
    cudaGetSymbolAddress((void**)&vtf, g_vtf);
    cudaGetSymbolAddress((void**)&oh,  g_oh);
    cudaGetSymbolAddress((void**)&ol,  g_ol);
    cudaGetSymbolAddress((void**)&wqf, g_wqf);
    cudaGetSymbolAddress((void**)&wkf, g_wkf);
    cudaGetSymbolAddress((void**)&wvh, g_wvh);
    cudaGetSymbolAddress((void**)&wvl, g_wvl);
    cudaGetSymbolAddress((void**)&woh, g_woh);
    cudaGetSymbolAddress((void**)&wol, g_wol);

    static int attr_set = 0;
    if (!attr_set) {
        cudaFuncSetAttribute(gemm_f16s,   cudaFuncAttributeMaxDynamicSharedMemorySize, GEMM1_SMEM);
        cudaFuncSetAttribute(gemm_bf3<0>, cudaFuncAttributeMaxDynamicSharedMemorySize, GEMM_SMEM);
        cudaFuncSetAttribute(gemm_bf3<1>, cudaFuncAttributeMaxDynamicSharedMemorySize, GEMM_SMEM);
        cudaFuncSetAttribute(flash_reg,   cudaFuncAttributeMaxDynamicSharedMemorySize, FLASH_SMEM);
        attr_set = 1;
    }

    {
        int total = XN4_ + 4 * WN4_;
        prepass_all<<<(total + 255) / 256, 256>>>(
            (const float4*)x,  (uint2*)xh, (uint2*)xl, (uint2*)xf,
            (const float4*)wq, (uint2*)wqf,
            (const float4*)wk, (uint2*)wkf,
            (const float4*)wv, (uint2*)wvh, (uint2*)wvl,
            (const float4*)wo, (uint2*)woh, (uint2*)wol);
    }

    dim3 g1(DM_ / 128, BSM / 128);   // (16, 32)
    dim3 g3(DM_ / 256, BSM / 128);   // (8, 32)

    gemm_f16s<<<g1, 256, GEMM1_SMEM>>>(xf, wqf, q);
    gemm_f16s<<<g1, 256, GEMM1_SMEM>>>(xf, wkf, k);
    gemm_bf3<1><<<g3, 512, GEMM_SMEM>>>(xh, xl, wvh, wvl, nullptr, vtf);

    {
        int nwarps = 2 * BSM * H_;
        norm_rope_split2<<<nwarps / 8, 256>>>(q, k, rope, qnw, knw, qh, ql, kh, kl);
    }

    flash_reg<<<dim3(S_ / 128, H_, B_), 256, FLASH_SMEM>>>(qh, ql, kh, kl, vtf, oh, ol);

    gemm_bf3<0><<<g3, 512, GEMM_SMEM>>>(oh, ol, woh, wol, out, nullptr);
}

// round 16
// speedup vs baseline: 1.0425x; 1.0425x over previous
#include <cuda_runtime.h>
#include <cuda_bf16.h>
#include <cuda_fp16.h>
#include <math.h>
#include <stdint.h>

#define B_   2
#define S_   2048
#define DM_  2048
#define H_   16
#define DH_  128
#define BSM  (B_ * S_)   // 4096 rows

// ---------------------------------------------------------------------------
// Scratch (static device globals — no allocation allowed)
// ---------------------------------------------------------------------------
__device__ __nv_bfloat16 g_xh[(size_t)BSM * DM_];
__device__ __nv_bfloat16 g_xl[(size_t)BSM * DM_];
__device__ __half        g_xf[(size_t)BSM * DM_];
__device__ __nv_bfloat16 g_qh[(size_t)BSM * DM_];   // [b][h][s][d] pre-scaled
__device__ __nv_bfloat16 g_ql[(size_t)BSM * DM_];
__device__ __nv_bfloat16 g_kh[(size_t)BSM * DM_];
__device__ __nv_bfloat16 g_kl[(size_t)BSM * DM_];
__device__ __half        g_vtf[(size_t)BSM * DM_];  // [b][h][d][s]
__device__ __nv_bfloat16 g_oh[(size_t)BSM * DM_];
__device__ __nv_bfloat16 g_ol[(size_t)BSM * DM_];
__device__ __half        g_wqf[(size_t)DM_ * DM_];
__device__ __half        g_wkf[(size_t)DM_ * DM_];
__device__ __nv_bfloat16 g_wvh[(size_t)DM_ * DM_];
__device__ __nv_bfloat16 g_wvl[(size_t)DM_ * DM_];
__device__ __nv_bfloat16 g_woh[(size_t)DM_ * DM_];
__device__ __nv_bfloat16 g_wol[(size_t)DM_ * DM_];

// ---------------------------------------------------------------------------
// Helpers
// ---------------------------------------------------------------------------
__device__ __forceinline__ void mma_bf16(float* c, const uint32_t* a, const uint32_t* b) {
    asm volatile(
        "mma.sync.aligned.m16n8k16.row.col.f32.bf16.bf16.f32 "
        "{%0,%1,%2,%3}, {%4,%5,%6,%7}, {%8,%9}, {%0,%1,%2,%3};"
        : "+f"(c[0]), "+f"(c[1]), "+f"(c[2]), "+f"(c[3])
        : "r"(a[0]), "r"(a[1]), "r"(a[2]), "r"(a[3]), "r"(b[0]), "r"(b[1]));
}
__device__ __forceinline__ void mma_f16(float* c, const uint32_t* a, const uint32_t* b) {
    asm volatile(
        "mma.sync.aligned.m16n8k16.row.col.f32.f16.f16.f32 "
        "{%0,%1,%2,%3}, {%4,%5,%6,%7}, {%8,%9}, {%0,%1,%2,%3};"
        : "+f"(c[0]), "+f"(c[1]), "+f"(c[2]), "+f"(c[3])
        : "r"(a[0]), "r"(a[1]), "r"(a[2]), "r"(a[3]), "r"(b[0]), "r"(b[1]));
}

__device__ __forceinline__ void ldsm4(uint32_t& r0, uint32_t& r1, uint32_t& r2,
                                      uint32_t& r3, uint32_t saddr) {
    asm volatile("ldmatrix.sync.aligned.m8n8.x4.shared.b16 {%0,%1,%2,%3}, [%4];"
                 : "=r"(r0), "=r"(r1), "=r"(r2), "=r"(r3) : "r"(saddr));
}

__device__ __forceinline__ uint32_t smem_u32(const void* p) {
    return (uint32_t)__cvta_generic_to_shared(p);
}

__device__ __forceinline__ void cp16(void* smem_dst, const void* gmem_src) {
    uint32_t sa = (uint32_t)__cvta_generic_to_shared(smem_dst);
    asm volatile("cp.async.cg.shared.global [%0], [%1], 16;" :: "r"(sa), "l"(gmem_src));
}
__device__ __forceinline__ void cp_commit() { asm volatile("cp.async.commit_group;"); }
__device__ __forceinline__ void cp_wait1() { asm volatile("cp.async.wait_group 1;"); }
__device__ __forceinline__ void cp_wait0() { asm volatile("cp.async.wait_group 0;"); }

__device__ __forceinline__ void bfsplit1(float x, __nv_bfloat16& h, __nv_bfloat16& l) {
    h = __float2bfloat16_rn(x);
    l = __float2bfloat16_rn(x - __bfloat162float(h));
}
__device__ __forceinline__ uint32_t packbf(__nv_bfloat16 e, __nv_bfloat16 o) {
    uint32_t lo = __bfloat16_as_ushort(e), hi = __bfloat16_as_ushort(o);
    return lo | (hi << 16);
}
__device__ __forceinline__ void packsplit2(float a, float b, uint32_t& wh, uint32_t& wl) {
    __nv_bfloat16 ha, la, hb, lb;
    bfsplit1(a, ha, la); bfsplit1(b, hb, lb);
    wh = packbf(ha, hb); wl = packbf(la, lb);
}
__device__ __forceinline__ uint32_t packh(__half a, __half b) {
    return (uint32_t)__half_as_ushort(a) | ((uint32_t)__half_as_ushort(b) << 16);
}
__device__ __forceinline__ void hpacksplit2(float a, float b, uint32_t& wh, uint32_t& wl) {
    __half ha = __float2half_rn(a), hb = __float2half_rn(b);
    __half la = __float2half_rn(a - __half2float(ha));
    __half lb = __float2half_rn(b - __half2float(hb));
    wh = packh(ha, hb); wl = packh(la, lb);
}

// ---------------------------------------------------------------------------
// Fused pre-pass (single launch)
// ---------------------------------------------------------------------------
#define XN4_ (BSM * DM_ / 4)
#define WN4_ (DM_ * DM_ / 4)

__global__ __launch_bounds__(256)
void prepass_all(
    const float4* __restrict__ x,  uint2* __restrict__ xh, uint2* __restrict__ xl,
    uint2* __restrict__ xf,
    const float4* __restrict__ wq, uint2* __restrict__ wqf,
    const float4* __restrict__ wk, uint2* __restrict__ wkf,
    const float4* __restrict__ wv, uint2* __restrict__ wvh, uint2* __restrict__ wvl,
    const float4* __restrict__ wo, uint2* __restrict__ woh, uint2* __restrict__ wol) {
    int i = blockIdx.x * blockDim.x + threadIdx.x;
    if (i < XN4_) {
        float4 v = x[i];
        __nv_bfloat16 h0, l0, h1, l1, h2, l2, h3, l3;
        bfsplit1(v.x, h0, l0); bfsplit1(v.y, h1, l1);
        bfsplit1(v.z, h2, l2); bfsplit1(v.w, h3, l3);
        xh[i] = make_uint2(packbf(h0, h1), packbf(h2, h3));
        xl[i] = make_uint2(packbf(l0, l1), packbf(l2, l3));
        xf[i] = make_uint2(packh(__float2half_rn(v.x), __float2half_rn(v.y)),
                           packh(__float2half_rn(v.z), __float2half_rn(v.w)));
        return;
    }
    int t = i - XN4_;
    int r = t >> 20;
    int j = t & (WN4_ - 1);
    if (r < 2) {
        float4 v = (r == 0 ? wq : wk)[j];
        uint2* dst = (r == 0 ? wqf : wkf);
        dst[j] = make_uint2(packh(__float2half_rn(v.x), __float2half_rn(v.y)),
                            packh(__float2half_rn(v.z), __float2half_rn(v.w)));
    } else {
        float4 v = (r == 2 ? wv : wo)[j];
        uint2* hi = (r == 2 ? wvh : woh);
        uint2* lo = (r == 2 ? wvl : wol);
        __nv_bfloat16 h0, l0, h1, l1, h2, l2, h3, l3;
        bfsplit1(v.x, h0, l0); bfsplit1(v.y, h1, l1);
        bfsplit1(v.z, h2, l2); bfsplit1(v.w, h3, l3);
        hi[j] = make_uint2(packbf(h0, h1), packbf(h2, h3));
        lo[j] = make_uint2(packbf(l0, l1), packbf(l2, l3));
    }
}

// ---------------------------------------------------------------------------
// fp16 SINGLE-PASS GEMM for wq AND wk (gridDim.z selects) with FUSED
// RMSNorm + RoPE + bf16-split epilogue.
// 128x128x32, 256 thr, 2 CTAs/SM, 3-stage pipeline, 1 sync/ktile.
// N-tile(128) == one head: norm reduction + rope pairing done in-CTA.
// RoPE partner (d ^ 64) lives in sibling warp (w ^ 4), same lane/slot.
// ---------------------------------------------------------------------------
#define TWB 2560
#define STG1W (2 * TWB)
#define GEMM1_SMEM (3 * STG1W * 4)   // 61440 B

__global__ __launch_bounds__(256, 2)
void gemm_qk_fused(const __half* __restrict__ A,
                   const __half* __restrict__ Wq, const __half* __restrict__ Wk,
                   const float* __restrict__ rope,
                   const float* __restrict__ qnw, const float* __restrict__ knw,
                   __nv_bfloat16* __restrict__ Qh, __nv_bfloat16* __restrict__ Ql,
                   __nv_bfloat16* __restrict__ Kh, __nv_bfloat16* __restrict__ Kl) {
    extern __shared__ uint32_t smw[];
    const uint32_t smem_b = smem_u32(smw);

    const int tid  = threadIdx.x;
    const int lane = tid & 31;
    const int w    = tid >> 5;
    const int wm   = w & 3;
    const int wn   = w >> 2;
    const int g    = lane >> 2;
    const int tg   = lane & 3;
    const int rb   = wm * 32;
    const int cb   = wn * 64;
    const int K    = DM_;
    const int z    = blockIdx.z;

    const __half* gA = A + (size_t)blockIdx.y * 128 * K;
    const __half* gB = (z ? Wk : Wq) + (size_t)blockIdx.x * 128 * K;

    const uint32_t a_off = (uint32_t)((rb + (lane & 15)) * 20 + (lane >> 4) * 4) * 4;
    const uint32_t b_off = (uint32_t)((cb + (lane & 7) + ((lane >> 4) & 1) * 8) * 20
                                      + ((lane >> 3) & 1) * 4) * 4;

    auto issue = [&](int stage, int k0) {
        uint32_t* base = smw + stage * STG1W;
#pragma unroll
        for (int p = 0; p < 2; p++) {
            int s   = p * 256 + tid;
            int row = s >> 2;
            int kq  = s & 3;
            int d   = row * 20 + kq * 4;
            size_t srcoff = (size_t)row * K + k0 + kq * 8;
            cp16(base + d,       gA + srcoff);
            cp16(base + TWB + d, gB + srcoff);
        }
        cp_commit();
    };

    float acc[2][8][4];
#pragma unroll
    for (int mt = 0; mt < 2; mt++)
#pragma unroll
        for (int nt = 0; nt < 8; nt++)
#pragma unroll
            for (int i = 0; i < 4; i++) acc[mt][nt][i] = 0.f;

    issue(0, 0);
    issue(1, 32);

    const int KT = K / 32;
    int stg = 0;
    for (int kt = 0; kt < KT; kt++) {
        if (kt == KT - 1) cp_wait0(); else cp_wait1();
        __syncthreads();
        if (kt + 2 < KT) issue((stg + 2) % 3, (kt + 2) * 32);

        const uint32_t tb = smem_b + stg * (STG1W * 4);
#pragma unroll
        for (int kc = 0; kc < 2; kc++) {
            const uint32_t kbb = kc * 32;
            uint32_t ah[2][4];
#pragma unroll
            for (int mt = 0; mt < 2; mt++)
                ldsm4(ah[mt][0], ah[mt][1], ah[mt][2], ah[mt][3],
                      tb + a_off + mt * (16 * 80) + kbb);
#pragma unroll
            for (int p = 0; p < 4; p++) {
                uint32_t bh[2][2];
                ldsm4(bh[0][0], bh[0][1], bh[1][0], bh[1][1],
                      tb + TWB * 4 + b_off + p * (16 * 80) + kbb);
#pragma unroll
                for (int q = 0; q < 2; q++)
#pragma unroll
                    for (int mt = 0; mt < 2; mt++)
                        mma_f16(acc[mt][2 * p + q], ah[mt], bh[q]);
            }
        }
        stg = (stg + 1) % 3;
    }

    // ================= fused epilogue: RMSNorm + RoPE + split =================
    __syncthreads();   // all warps done reading pipeline smem

    float* part = (float*)smw;          // [2][128] partial sums of squares
    float* exch = (float*)smw + 256;    // [8][32][16] fp32 exchange (16 KB)

    // per-thread sum of squares, 4 row-slots (mt, rh)
    float s2[4] = {0.f, 0.f, 0.f, 0.f};
#pragma unroll
    for (int mt = 0; mt < 2; mt++)
#pragma unroll
        for (int nt = 0; nt < 8; nt++) {
            s2[mt * 2 + 0] += acc[mt][nt][0] * acc[mt][nt][0]
                            + acc[mt][nt][1] * acc[mt][nt][1];
            s2[mt * 2 + 1] += acc[mt][nt][2] * acc[mt][nt][2]
                            + acc[mt][nt][3] * acc[mt][nt][3];
        }
#pragma unroll
    for (int o = 1; o < 4; o <<= 1)
#pragma unroll
        for (int i = 0; i < 4; i++) s2[i] += __shfl_xor_sync(0xFFFFFFFFu, s2[i], o);
    if (tg == 0) {
#pragma unroll
        for (int mt = 0; mt < 2; mt++)
#pragma unroll
            for (int rh = 0; rh < 2; rh++)
                part[wn * 128 + rb + mt * 16 + rh * 8 + g] = s2[mt * 2 + rh];
    }
    __syncthreads();

    float inv[4];
#pragma unroll
    for (int mt = 0; mt < 2; mt++)
#pragma unroll
        for (int rh = 0; rh < 2; rh++) {
            int r = rb + mt * 16 + rh * 8 + g;
            float tot = part[r] + part[128 + r];
            inv[mt * 2 + rh] = rsqrtf(tot * (1.0f / 128.0f) + 1e-6f);
        }

    // norm weights for this thread's 16 columns
    const float* nw = z ? knw : qnw;
    float wv0[8], wv1[8];
#pragma unroll
    for (int nt = 0; nt < 8; nt++) {
        float2 ww = *(const float2*)(nw + cb + nt * 8 + tg * 2);
        wv0[nt] = ww.x; wv1[nt] = ww.y;
    }

    const float scale = z ? 1.0f : 0.08838834764831845f;
    const int hh = blockIdx.x;
    const int pw = w ^ 4;
    __nv_bfloat16* Oh = z ? Kh : Qh;
    __nv_bfloat16* Ol = z ? Kl : Ql;

#pragma unroll
    for (int mt = 0; mt < 2; mt++)
#pragma unroll
        for (int rh = 0; rh < 2; rh++) {
            float v[16];
            float iv = inv[mt * 2 + rh];
#pragma unroll
            for (int nt = 0; nt < 8; nt++) {
                v[2 * nt]     = acc[mt][nt][rh * 2 + 0] * iv * wv0[nt];
                v[2 * nt + 1] = acc[mt][nt][rh * 2 + 1] * iv * wv1[nt];
            }
            __syncthreads();   // previous chunk's reads complete
            float* eslot = exch + ((size_t)w * 32 + lane) * 16;
#pragma unroll
            for (int k = 0; k < 16; k++) eslot[k] = v[k];
            __syncthreads();
            const float* pslot = exch + ((size_t)pw * 32 + lane) * 16;
            float pv[16];
#pragma unroll
            for (int k = 0; k < 16; k++) pv[k] = pslot[k];

            int rloc  = rb + mt * 16 + rh * 8 + g;
            int token = blockIdx.y * 128 + rloc;
            int bb = token >> 11, s = token & 2047;
            const float* f = rope + (size_t)s * 256;
            size_t obase = ((size_t)(bb * 16 + hh) * 2048 + s) * 128;
#pragma unroll
            for (int nt = 0; nt < 8; nt++) {
                int d0 = cb + nt * 8 + tg * 2;
                float y[2];
#pragma unroll
                for (int c = 0; c < 2; c++) {
                    int i = (d0 + c) & 63;
                    float4 fc = *(const float4*)(f + i * 4);
                    float val = v[2 * nt + c], pval = pv[2 * nt + c];
                    y[c] = (wn == 0) ? (fc.x * val + fc.y * pval)
                                     : (fc.z * pval + fc.w * val);
                    y[c] *= scale;
                }
                uint32_t wh_, wl_;
                packsplit2(y[0], y[1], wh_, wl_);
                *(uint32_t*)(Oh + obase + d0) = wh_;
                *(uint32_t*)(Ol + obase + d0) = wl_;
            }
        }
}

// ---------------------------------------------------------------------------
// bf16x3 GEMM (wv, wo): 128Mx256N, 512 threads, 3-stage, 1 sync/ktile.
// OUT=0: fp32 C. OUT=1: V path — fp16 single transposed per-head store.
// ---------------------------------------------------------------------------
#define AT_W 2560
#define BT_W 5120
#define STG3W (2 * AT_W + 2 * BT_W)
#define GEMM_SMEM (3 * STG3W * 4)

template<int OUT>
__global__ __launch_bounds__(512, 1)
void gemm_bf3(const __nv_bfloat16* __restrict__ Ah, const __nv_bfloat16* __restrict__ Al,
              const __nv_bfloat16* __restrict__ Bh, const __nv_bfloat16* __restrict__ Bl,
              float* __restrict__ C, __half* __restrict__ Vf) {
    extern __shared__ uint32_t smw[];
    const uint32_t smem_b = smem_u32(smw);

    const int tid  = threadIdx.x;
    const int lane = tid & 31;
    const int w    = tid >> 5;
    const int wm   = w & 3;
    const int wn   = w >> 2;
    const int g    = lane >> 2;
    const int tg   = lane & 3;
    const int rb   = wm * 32;
    const int cb   = wn * 64;
    const int K    = DM_;

    const __nv_bfloat16* gAh = Ah + (size_t)blockIdx.y * 128 * K;
    const __nv_bfloat16* gAl = Al + (size_t)blockIdx.y * 128 * K;
    const __nv_bfloat16* gBh = Bh + (size_t)blockIdx.x * 256 * K;
    const __nv_bfloat16* gBl = Bl + (size_t)blockIdx.x * 256 * K;

    const uint32_t a_off = (uint32_t)((rb + (lane & 15)) * 20 + (lane >> 4) * 4) * 4;
    const uint32_t b_off = (uint32_t)((cb + (lane & 7) + ((lane >> 4) & 1) * 8) * 20
                                      + ((lane >> 3) & 1) * 4) * 4;

    auto issue = [&](int stage, int k0) {
        uint32_t* base = smw + stage * STG3W;
#pragma unroll
        for (int p = 0; p < 6; p++) {
            int c    = p * 512 + tid;
            int row  = c >> 2;
            int kq   = c & 3;
            const __nv_bfloat16* src;
            uint32_t* dst;
            if (row < 256) {
                int r = row & 127;
                src = (row < 128 ? gAh : gAl) + (size_t)r * K + k0 + kq * 8;
                dst = base + (row < 128 ? 0 : AT_W) + r * 20 + kq * 4;
            } else {
                int r = (row - 256) & 255;
                src = (row < 512 ? gBh : gBl) + (size_t)r * K + k0 + kq * 8;
                dst = base + 2 * AT_W + (row < 512 ? 0 : BT_W) + r * 20 + kq * 4;
            }
            cp16(dst, src);
        }
        cp_commit();
    };

    float acc[2][8][4];
#pragma unroll
    for (int mt = 0; mt < 2; mt++)
#pragma unroll
        for (int nt = 0; nt < 8; nt++)
#pragma unroll
            for (int i = 0; i < 4; i++) acc[mt][nt][i] = 0.f;

    issue(0, 0);
    issue(1, 32);

    const int KT = K / 32;
    int stg = 0;
    for (int kt = 0; kt < KT; kt++) {
        if (kt == KT - 1) cp_wait0(); else cp_wait1();
        __syncthreads();
        if (kt + 2 < KT) issue((stg + 2) % 3, (kt + 2) * 32);

        const uint32_t tb  = smem_b + stg * (STG3W * 4);
        const uint32_t tbB = tb + 2 * AT_W * 4;
#pragma unroll
        for (int kc = 0; kc < 2; kc++) {
            const uint32_t kbb = kc * 32;
            uint32_t ah[2][4], al[2][4];
#pragma unroll
            for (int mt = 0; mt < 2; mt++) {
                ldsm4(ah[mt][0], ah[mt][1], ah[mt][2], ah[mt][3],
                      tb + a_off + mt * (16 * 80) + kbb);
                ldsm4(al[mt][0], al[mt][1], al[mt][2], al[mt][3],
                      tb + AT_W * 4 + a_off + mt * (16 * 80) + kbb);
            }
#pragma unroll
            for (int p = 0; p < 4; p++) {
                uint32_t bh[2][2], bl[2][2];
                ldsm4(bh[0][0], bh[0][1], bh[1][0], bh[1][1],
                      tbB + b_off + p * (16 * 80) + kbb);
                ldsm4(bl[0][0], bl[0][1], bl[1][0], bl[1][1],
                      tbB + BT_W * 4 + b_off + p * (16 * 80) + kbb);
#pragma unroll
                for (int q = 0; q < 2; q++)
#pragma unroll
                    for (int mt = 0; mt < 2; mt++)
                        mma_bf16(acc[mt][2 * p + q], ah[mt], bh[q]);
#pragma unroll
                for (int q = 0; q < 2; q++)
#pragma unroll
                    for (int mt = 0; mt < 2; mt++)
                        mma_bf16(acc[mt][2 * p + q], ah[mt], bl[q]);
#pragma unroll
                for (int q = 0; q < 2; q++)
#pragma unroll
                    for (int mt = 0; mt < 2; mt++)
                        mma_bf16(acc[mt][2 * p + q], al[mt], bh[q]);
            }
        }
        stg = (stg + 1) % 3;
    }

#pragma unroll
    for (int mt = 0; mt < 2; mt++)
#pragma unroll
        for (int nt = 0; nt < 8; nt++) {
            int row = blockIdx.y * 128 + rb + mt * 16 + g;
            int col = blockIdx.x * 256 + cb + nt * 8 + tg * 2;
            if (OUT == 0) {
                *(float2*)(C + (size_t)row * DM_ + col) =
                    make_float2(acc[mt][nt][0], acc[mt][nt][1]);
                *(float2*)(C + (size_t)(row + 8) * DM_ + col) =
                    make_float2(acc[mt][nt][2], acc[mt][nt][3]);
            } else {
                int hh = col >> 7, d = col & 127;
#pragma unroll
                for (int rr = 0; rr < 2; rr++) {
                    int r = row + rr * 8;
                    int bb = r >> 11, s = r & 2047;
                    size_t base = ((size_t)(bb * 16 + hh) * 128 + d) * 2048 + s;
                    Vf[base]        = __float2half_rn(acc[mt][nt][rr * 2]);
                    Vf[base + 2048] = __float2half_rn(acc[mt][nt][rr * 2 + 1]);
                }
            }
        }
}

// ---------------------------------------------------------------------------
// Register-resident flash attention (R13/R15 design).
// QK: bf16x3 pass-major. PV: fp16 x2 pass-major.
// 3-stage KV pipeline, single sync/ktile, issue-before-compute.
// ---------------------------------------------------------------------------
#define FQW 68
#define FVW 36
#define QWORDS (128 * FQW)
#define KTILEW (64 * FQW)
#define VTILEW (128 * FVW)
#define STGW   (2 * KTILEW + VTILEW)
#define OFF_STG (2 * QWORDS)
#define FLASH_SMEM ((OFF_STG + 3 * STGW) * 4)   // 229376 B

__global__ __launch_bounds__(256, 1)
void flash_reg(const __nv_bfloat16* __restrict__ Qh, const __nv_bfloat16* __restrict__ Ql,
               const __nv_bfloat16* __restrict__ Kh, const __nv_bfloat16* __restrict__ Kl,
               const __half* __restrict__ Vtf,
               __nv_bfloat16* __restrict__ Oh, __nv_bfloat16* __restrict__ Ol) {
    extern __shared__ uint32_t smw[];

    const int tid  = threadIdx.x;
    const int lane = tid & 31;
    const int w    = tid >> 5;
    const int g    = lane >> 2;
    const int tg   = lane & 3;
    const int q0   = blockIdx.x * 128;
    const int h    = blockIdx.y;
    const int b    = blockIdx.z;
    const int rw   = w * 16;

    const size_t headQ = ((size_t)(b * H_ + h) * S_) * DH_;
    const __nv_bfloat16* gQh = Qh + headQ + (size_t)q0 * DH_;
    const __nv_bfloat16* gQl = Ql + headQ + (size_t)q0 * DH_;
    const __nv_bfloat16* gKh = Kh + headQ;
    const __nv_bfloat16* gKl = Kl + headQ;
    const size_t headV = ((size_t)(b * H_ + h) * DH_) * S_;
    const __half* gVtf = Vtf + headV;

    {
#pragma unroll
        for (int p = 0; p < 16; p++) {
            int t   = p * 256 + tid;
            int reg = t >> 11;
            int idx = t & 2047;
            int row = idx >> 4, ch = idx & 15;
            const __nv_bfloat16* src = (reg ? gQl : gQh) + (size_t)row * DH_ + ch * 8;
            cp16(smw + reg * QWORDS + row * FQW + ch * 4, src);
        }
        cp_commit();
    }

    auto issue_kv = [&](int stage, int j0) {
        uint32_t* base = smw + OFF_STG + stage * STGW;
#pragma unroll
        for (int p = 0; p < 12; p++) {
            int t   = p * 256 + tid;
            int reg = t >> 10;
            int idx = t & 1023;
            if (reg < 2) {
                int row = idx >> 4, ch = idx & 15;
                const __nv_bfloat16* src = (reg ? gKl : gKh) + (size_t)(j0 + row) * DH_ + ch * 8;
                cp16(base + reg * KTILEW + row * FQW + ch * 4, src);
            } else {
                int d = idx >> 3, ch = idx & 7;
                const __half* src = gVtf + (size_t)d * S_ + j0 + ch * 8;
                cp16(base + 2 * KTILEW + d * FVW + ch * 4, src);
            }
        }
        cp_commit();
    };

    issue_kv(0, 0);
    issue_kv(1, 64);

    float oacc[16][4];
#pragma unroll
    for (int nt = 0; nt < 16; nt++)
#pragma unroll
        for (int i = 0; i < 4; i++) oacc[nt][i] = 0.f;
    float m0 = -1e30f, m1 = -1e30f, l0 = 0.f, l1 = 0.f;

    const int NKT = S_ / 64;
    int stg = 0;
    for (int kt = 0; kt < NKT; kt++) {
        if (kt == NKT - 1) cp_wait0(); else cp_wait1();
        __syncthreads();
        if (kt + 2 < NKT) issue_kv((stg + 2) % 3, (kt + 2) * 64);

        const uint32_t* Ksh = smw + OFF_STG + stg * STGW;
        const uint32_t* Ksl = Ksh + KTILEW;
        const uint32_t* Vsf = Ksh + 2 * KTILEW;

        float sc[8][4];
#pragma unroll
        for (int nt = 0; nt < 8; nt++)
#pragma unroll
            for (int i = 0; i < 4; i++) sc[nt][i] = 0.f;

#pragma unroll
        for (int c = 0; c < 8; c++) {
            int q0w = (rw + g) * FQW + c * 8 + tg;
            int q1w = q0w + 8 * FQW;
            uint32_t ah[4] = { smw[q0w], smw[q1w], smw[q0w + 4], smw[q1w + 4] };
            uint32_t al[4] = { smw[QWORDS + q0w], smw[QWORDS + q1w],
                               smw[QWORDS + q0w + 4], smw[QWORDS + q1w + 4] };
            uint32_t kh[8][2], kl[8][2];
#pragma unroll
            for (int nt = 0; nt < 8; nt++) {
                int n = (nt * 8 + g) * FQW + c * 8 + tg;
                kh[nt][0] = Ksh[n]; kh[nt][1] = Ksh[n + 4];
                kl[nt][0] = Ksl[n]; kl[nt][1] = Ksl[n + 4];
            }
#pragma unroll
            for (int nt = 0; nt < 8; nt++) mma_bf16(sc[nt], ah, kh[nt]);
#pragma unroll
            for (int nt = 0; nt < 8; nt++) mma_bf16(sc[nt], ah, kl[nt]);
#pragma unroll
            for (int nt = 0; nt < 8; nt++) mma_bf16(sc[nt], al, kh[nt]);
        }

        {
            float mx0 = sc[0][0], mx1 = sc[0][2];
#pragma unroll
            for (int j = 0; j < 8; j++) {
                mx0 = fmaxf(mx0, fmaxf(sc[j][0], sc[j][1]));
                mx1 = fmaxf(mx1, fmaxf(sc[j][2], sc[j][3]));
            }
            mx0 = fmaxf(mx0, __shfl_xor_sync(0xFFFFFFFFu, mx0, 1));
            mx0 = fmaxf(mx0, __shfl_xor_sync(0xFFFFFFFFu, mx0, 2));
            mx1 = fmaxf(mx1, __shfl_xor_sync(0xFFFFFFFFu, mx1, 1));
            mx1 = fmaxf(mx1, __shfl_xor_sync(0xFFFFFFFFu, mx1, 2));
            float nm0 = fmaxf(m0, mx0), nm1 = fmaxf(m1, mx1);
            float a0 = __expf(m0 - nm0), a1 = __expf(m1 - nm1);
            m0 = nm0; m1 = nm1;
            float s0 = 0.f, s1 = 0.f;
#pragma unroll
            for (int j = 0; j < 8; j++) {
                sc[j][0] = __expf(sc[j][0] - m0); sc[j][1] = __expf(sc[j][1] - m0);
                sc[j][2] = __expf(sc[j][2] - m1); sc[j][3] = __expf(sc[j][3] - m1);
                s0 += sc[j][0] + sc[j][1];
                s1 += sc[j][2] + sc[j][3];
            }
            s0 += __shfl_xor_sync(0xFFFFFFFFu, s0, 1);
            s0 += __shfl_xor_sync(0xFFFFFFFFu, s0, 2);
            s1 += __shfl_xor_sync(0xFFFFFFFFu, s1, 1);
            s1 += __shfl_xor_sync(0xFFFFFFFFu, s1, 2);
            l0 = l0 * a0 + s0;
            l1 = l1 * a1 + s1;
#pragma unroll
            for (int nt = 0; nt < 16; nt++) {
                oacc[nt][0] *= a0; oacc[nt][1] *= a0;
                oacc[nt][2] *= a1; oacc[nt][3] *= a1;
            }
        }

#pragma unroll
        for (int c = 0; c < 4; c++) {
            uint32_t ph[4], pl[4];
            hpacksplit2(sc[2 * c][0],     sc[2 * c][1],     ph[0], pl[0]);
            hpacksplit2(sc[2 * c][2],     sc[2 * c][3],     ph[1], pl[1]);
            hpacksplit2(sc[2 * c + 1][0], sc[2 * c + 1][1], ph[2], pl[2]);
            hpacksplit2(sc[2 * c + 1][2], sc[2 * c + 1][3], ph[3], pl[3]);
            uint32_t vv[16][2];
#pragma unroll
            for (int nt = 0; nt < 16; nt++) {
                int n = (nt * 8 + g) * FVW + c * 8 + tg;
                vv[nt][0] = Vsf[n]; vv[nt][1] = Vsf[n + 4];
            }
#pragma unroll
            for (int nt = 0; nt < 16; nt++) mma_f16(oacc[nt], ph, vv[nt]);
#pragma unroll
            for (int nt = 0; nt < 16; nt++) mma_f16(oacc[nt], pl, vv[nt]);
        }

        stg = (stg + 1) % 3;
    }

    {
        float li0 = 1.0f / l0, li1 = 1.0f / l1;
        size_t tok0 = (size_t)(b * S_ + q0 + rw + g) * DM_ + h * DH_;
        size_t tok1 = tok0 + 8 * DM_;
#pragma unroll
        for (int nt = 0; nt < 16; nt++) {
            int col = nt * 8 + tg * 2;
            uint32_t wh, wl;
            packsplit2(oacc[nt][0] * li0, oacc[nt][1] * li0, wh, wl);
            *(uint32_t*)(Oh + tok0 + col) = wh;
            *(uint32_t*)(Ol + tok0 + col) = wl;
            packsplit2(oacc[nt][2] * li1, oacc[nt][3] * li1, wh, wl);
            *(uint32_t*)(Oh + tok1 + col) = wh;
            *(uint32_t*)(Ol + tok1 + col) = wl;
        }
    }
}

// ---------------------------------------------------------------------------
extern "C" void kernel_launch(void* const* d_in, const int* in_sizes, int n_in,
                              void* d_out, int out_size) {
    const float* x    = (const float*)d_in[0];
    const float* rope = (const float*)d_in[1];
    const float* wq   = (const float*)d_in[2];
    const float* wk   = (const float*)d_in[3];
    const float* wv   = (const float*)d_in[4];
    const float* wo   = (const float*)d_in[5];
    const float* qnw  = (const float*)d_in[6];
    const float* knw  = (const float*)d_in[7];
    float* out = (float*)d_out;

    __nv_bfloat16 *xh, *xl, *qh, *ql, *kh, *kl, *oh, *ol;
    __nv_bfloat16 *wvh, *wvl, *woh, *wol;
    __half *xf, *wqf, *wkf, *vtf;
    cudaGetSymbolAddress((void**)&xh,  g_xh);
    cudaGetSymbolAddress((void**)&xl,  g_xl);
    cudaGetSymbolAddress((void**)&xf,  g_xf);
    cudaGetSymbolAddress((void**)&qh,  g_qh);
    cudaGetSymbolAddress((void**)&ql,  g_ql);
    cudaGetSymbolAddress((void**)&kh,  g_kh);
    cudaGetSymbolAddress((void**)&kl,  g_kl);
    cudaGetSymbolAddress((void**)&vtf, g_vtf);
    cudaGetSymbolAddress((void**)&oh,  g_oh);
    cudaGetSymbolAddress((void**)&ol,  g_ol);
    cudaGetSymbolAddress((void**)&wqf, g_wqf);
    cudaGetSymbolAddress((void**)&wkf, g_wkf);
    cudaGetSymbolAddress((void**)&wvh, g_wvh);
    cudaGetSymbolAddress((void**)&wvl, g_wvl);
    cudaGetSymbolAddress((void**)&woh, g_woh);
    cudaGetSymbolAddress((void**)&wol, g_wol);

    static int attr_set = 0;
    if (!attr_set) {
        cudaFuncSetAttribute(gemm_qk_fused, cudaFuncAttributeMaxDynamicSharedMemorySize, GEMM1_SMEM);
        cudaFuncSetAttribute(gemm_bf3<0>,   cudaFuncAttributeMaxDynamicSharedMemorySize, GEMM_SMEM);
        cudaFuncSetAttribute(gemm_bf3<1>,   cudaFuncAttributeMaxDynamicSharedMemorySize, GEMM_SMEM);
        cudaFuncSetAttribute(flash_reg,     cudaFuncAttributeMaxDynamicSharedMemorySize, FLASH_SMEM);
        attr_set = 1;
    }

    {
        int total = XN4_ + 4 * WN4_;
        prepass_all<<<(total + 255) / 256, 256>>>(
            (const float4*)x,  (uint2*)xh, (uint2*)xl, (uint2*)xf,
            (const float4*)wq, (uint2*)wqf,
            (const float4*)wk, (uint2*)wkf,
            (const float4*)wv, (uint2*)wvh, (uint2*)wvl,
            (const float4*)wo, (uint2*)woh, (uint2*)wol);
    }

    dim3 gqk(DM_ / 128, BSM / 128, 2);   // (16, 32, 2)
    dim3 g3(DM_ / 256, BSM / 128);       // (8, 32)

    gemm_qk_fused<<<gqk, 256, GEMM1_SMEM>>>(xf, wqf, wkf, rope, qnw, knw,
                                            qh, ql, kh, kl);
    gemm_bf3<1><<<g3, 512, GEMM_SMEM>>>(xh, xl, wvh, wvl, nullptr, vtf);

    flash_reg<<<dim3(S_ / 128, H_, B_), 256, FLASH_SMEM>>>(qh, ql, kh, kl, vtf, oh, ol);

    gemm_bf3<0><<<g3, 512, GEMM_SMEM>>>(oh, ol, woh, wol, out, nullptr);
}